// round 1
// baseline (speedup 1.0000x reference)
#include <cuda_runtime.h>

// Problem constants (shapes fixed by the reference: B=4,S=64 -> M=256)
#define M_DIM   256
#define K_DIM   4096
#define N_DIM   11008
#define G_DIM   32          // K_DIM / GROUP_SIZE
#define GROUPSZ 128
#define R_DIM   16          // LORA_R
#define SCALING 2.0f        // LORA_ALPHA / LORA_R = 32/16

// Scratch for xa = SCALING * (x @ lora_A^T)  [256 x 16]
__device__ float g_xa[M_DIM * R_DIM];

// ---------------------------------------------------------------------------
// Kernel 1: xa[m, r] = SCALING * sum_k x[m,k] * lora_A[r,k]
// One block per m-row, 128 threads; each thread strides K and keeps 16 accs.
// ---------------------------------------------------------------------------
__global__ void lora_xa_kernel(const float* __restrict__ x,
                               const float* __restrict__ loraA) {
    const int m   = blockIdx.x;
    const int tid = threadIdx.x;

    float acc[R_DIM];
#pragma unroll
    for (int r = 0; r < R_DIM; r++) acc[r] = 0.f;

    const float* xr = x + (size_t)m * K_DIM;
    for (int k = tid; k < K_DIM; k += 128) {
        float xv = xr[k];
#pragma unroll
        for (int r = 0; r < R_DIM; r++)
            acc[r] = fmaf(xv, loraA[r * K_DIM + k], acc[r]);
    }

    __shared__ float red[R_DIM][128];
#pragma unroll
    for (int r = 0; r < R_DIM; r++) red[r][tid] = acc[r];
    __syncthreads();

#pragma unroll
    for (int s = 64; s > 0; s >>= 1) {
        if (tid < s) {
#pragma unroll
            for (int r = 0; r < R_DIM; r++) red[r][tid] += red[r][tid + s];
        }
        __syncthreads();
    }
    if (tid < R_DIM) g_xa[m * R_DIM + tid] = red[tid][0] * SCALING;
}

// ---------------------------------------------------------------------------
// Kernel 2: out = x @ dequant(qweight)^T + xa @ lora_B^T
// 128x128 tile, BK=16, 256 threads, 8x8 register micro-tile per thread.
// Dequant ((q - z) * s) is folded into the SMEM B-tile fill; inner loop is
// pure FFMA. LoRA is an extra 16-deep "k-step" in the epilogue reusing the
// same SMEM layout and compute body.
// ---------------------------------------------------------------------------
#define BM 128
#define BN 128
#define BK 16

__global__ __launch_bounds__(256, 2)
void gptq_lora_gemm(const float* __restrict__ x,
                    const int*   __restrict__ qw,
                    const float* __restrict__ scales,
                    const int*   __restrict__ zeros,
                    const float* __restrict__ loraB,
                    float*       __restrict__ out) {
    __shared__ float As[BK][BM];   // As[k][m]
    __shared__ float Bs[BK][BN];   // Bs[k][n]

    const int m0  = blockIdx.y * BM;
    const int n0  = blockIdx.x * BN;
    const int tid = threadIdx.x;
    const int tx  = tid & 15;      // 16 cols of threads
    const int ty  = tid >> 4;      // 16 rows of threads

    float acc[8][8];
#pragma unroll
    for (int i = 0; i < 8; i++)
#pragma unroll
        for (int j = 0; j < 8; j++) acc[i][j] = 0.f;

    const int am = m0 + ty * 8;    // this thread's 8 output rows base
    const int bn = n0 + tx * 8;    // this thread's 8 output cols base

    for (int kt = 0; kt < K_DIM / BK; kt++) {
        const int k0 = kt * BK;
        const int g  = k0 >> 7;    // group index (BK=16 divides GROUPSZ=128)

        // ---- fill SMEM: A tile (x) and dequantized B tile (qweight) ----
#pragma unroll
        for (int i = 0; i < 2; i++) {
            const int idx = tid + i * 256;     // 512 float4/int4 loads total
            const int row = idx >> 2;          // 0..127
            const int c4  = (idx & 3) * 4;     // 0,4,8,12

            float4 va = *reinterpret_cast<const float4*>(
                x + (size_t)(m0 + row) * K_DIM + k0 + c4);
            As[c4 + 0][row] = va.x;
            As[c4 + 1][row] = va.y;
            As[c4 + 2][row] = va.z;
            As[c4 + 3][row] = va.w;

            int4 q = *reinterpret_cast<const int4*>(
                qw + (size_t)(n0 + row) * K_DIM + k0 + c4);
            const float s = scales[(size_t)(n0 + row) * G_DIM + g];
            const float z = (float)zeros[(size_t)(n0 + row) * G_DIM + g];
            Bs[c4 + 0][row] = ((float)q.x - z) * s;
            Bs[c4 + 1][row] = ((float)q.y - z) * s;
            Bs[c4 + 2][row] = ((float)q.z - z) * s;
            Bs[c4 + 3][row] = ((float)q.w - z) * s;
        }
        __syncthreads();

        // ---- compute: 16 pure-FFMA steps ----
#pragma unroll
        for (int k = 0; k < BK; k++) {
            float a[8], b[8];
            *reinterpret_cast<float4*>(a)     = *reinterpret_cast<const float4*>(&As[k][ty * 8]);
            *reinterpret_cast<float4*>(a + 4) = *reinterpret_cast<const float4*>(&As[k][ty * 8 + 4]);
            *reinterpret_cast<float4*>(b)     = *reinterpret_cast<const float4*>(&Bs[k][tx * 8]);
            *reinterpret_cast<float4*>(b + 4) = *reinterpret_cast<const float4*>(&Bs[k][tx * 8 + 4]);
#pragma unroll
            for (int i = 0; i < 8; i++)
#pragma unroll
                for (int j = 0; j < 8; j++)
                    acc[i][j] = fmaf(a[i], b[j], acc[i][j]);
        }
        __syncthreads();
    }

    // ---- LoRA epilogue: one extra 16-deep step with A<-g_xa, B<-lora_B ----
    {
#pragma unroll
        for (int i = 0; i < 2; i++) {
            const int idx = tid + i * 256;
            const int row = idx >> 2;
            const int c4  = (idx & 3) * 4;

            float4 va = *reinterpret_cast<const float4*>(g_xa + (m0 + row) * R_DIM + c4);
            As[c4 + 0][row] = va.x;
            As[c4 + 1][row] = va.y;
            As[c4 + 2][row] = va.z;
            As[c4 + 3][row] = va.w;

            float4 vb = *reinterpret_cast<const float4*>(
                loraB + (size_t)(n0 + row) * R_DIM + c4);
            Bs[c4 + 0][row] = vb.x;
            Bs[c4 + 1][row] = vb.y;
            Bs[c4 + 2][row] = vb.z;
            Bs[c4 + 3][row] = vb.w;
        }
        __syncthreads();

#pragma unroll
        for (int k = 0; k < R_DIM; k++) {
            float a[8], b[8];
            *reinterpret_cast<float4*>(a)     = *reinterpret_cast<const float4*>(&As[k][ty * 8]);
            *reinterpret_cast<float4*>(a + 4) = *reinterpret_cast<const float4*>(&As[k][ty * 8 + 4]);
            *reinterpret_cast<float4*>(b)     = *reinterpret_cast<const float4*>(&Bs[k][tx * 8]);
            *reinterpret_cast<float4*>(b + 4) = *reinterpret_cast<const float4*>(&Bs[k][tx * 8 + 4]);
#pragma unroll
            for (int i = 0; i < 8; i++)
#pragma unroll
                for (int j = 0; j < 8; j++)
                    acc[i][j] = fmaf(a[i], b[j], acc[i][j]);
        }
    }

    // ---- store 8x8 per thread (two float4 per row) ----
#pragma unroll
    for (int i = 0; i < 8; i++) {
        float* orow = out + (size_t)(am + i) * N_DIM + bn;
        float4 v0 = make_float4(acc[i][0], acc[i][1], acc[i][2], acc[i][3]);
        float4 v1 = make_float4(acc[i][4], acc[i][5], acc[i][6], acc[i][7]);
        *reinterpret_cast<float4*>(orow)     = v0;
        *reinterpret_cast<float4*>(orow + 4) = v1;
    }
}

// ---------------------------------------------------------------------------
// kernel_launch
// Inputs (metadata order): x, qweight, scales, zeros, lora_A, lora_B
// Output: float32 [256, 11008]
// ---------------------------------------------------------------------------
extern "C" void kernel_launch(void* const* d_in, const int* in_sizes, int n_in,
                              void* d_out, int out_size) {
    const float* x      = (const float*)d_in[0];
    const int*   qw     = (const int*)  d_in[1];
    const float* scales = (const float*)d_in[2];
    const int*   zeros  = (const int*)  d_in[3];
    const float* loraA  = (const float*)d_in[4];
    const float* loraB  = (const float*)d_in[5];
    float*       out    = (float*)d_out;

    lora_xa_kernel<<<M_DIM, 128>>>(x, loraA);

    dim3 grid(N_DIM / BN, M_DIM / BM);   // 86 x 2
    gptq_lora_gemm<<<grid, 256>>>(x, qw, scales, zeros, loraB, out);
}

// round 3
// speedup vs baseline: 2.1675x; 2.1675x over previous
#include <cuda_runtime.h>
#include <cuda_bf16.h>
#include <cstdint>

// ---------------------------------------------------------------------------
// Problem constants
// ---------------------------------------------------------------------------
#define M_DIM 256
#define K_DIM 4096
#define N_DIM 11008
#define G_DIM 32
#define R_DIM 16
#define SCALING 2.0f

#define BM 128
#define BN 128
#define BK 32
#define KT (K_DIM / BK)     // 128

// SMEM byte offsets. Tiles are [128 rows][32 k] bf16 with row pitch 80 bytes
// (80 = 16*5 -> every (row,k8) address is 16B aligned; row stride of 20 banks
// makes ldmatrix 8-row phases conflict-free).
#define PITCH 80
#define SA_HI 0
#define SA_LO 10240
#define SB_HI 20480
#define SB_LO 30720
#define SXA   40960         // lora xa tile:   [128][16] bf16, pitch 32B
#define SLB   45056         // lora B tile:    [128][16] bf16, pitch 32B
#define SMEM_BYTES 49152

// LoRA intermediate: xa = SCALING * (x @ lora_A^T), [256 x 16] fp32
__device__ float g_xa[M_DIM * R_DIM];

// ---------------------------------------------------------------------------
// helpers (family-common PTX only: ldmatrix sm_75+, mma.sync bf16 sm_80+)
// ---------------------------------------------------------------------------
__device__ __forceinline__ uint32_t smem_u32(const void* p) {
    uint32_t a;
    asm("{ .reg .u64 t; cvta.to.shared.u64 t, %1; cvt.u32.u64 %0, t; }"
        : "=r"(a) : "l"(p));
    return a;
}

__device__ __forceinline__ void ldsm_x4(uint32_t addr, uint32_t* r) {
    asm volatile("ldmatrix.sync.aligned.m8n8.x4.shared.b16 {%0,%1,%2,%3}, [%4];"
                 : "=r"(r[0]), "=r"(r[1]), "=r"(r[2]), "=r"(r[3]) : "r"(addr));
}
__device__ __forceinline__ void ldsm_x2(uint32_t addr, uint32_t* r) {
    asm volatile("ldmatrix.sync.aligned.m8n8.x2.shared.b16 {%0,%1}, [%2];"
                 : "=r"(r[0]), "=r"(r[1]) : "r"(addr));
}
__device__ __forceinline__ void mma_bf16(float* c, const uint32_t* a, const uint32_t* b) {
    asm volatile(
        "mma.sync.aligned.m16n8k16.row.col.f32.bf16.bf16.f32 "
        "{%0,%1,%2,%3}, {%4,%5,%6,%7}, {%8,%9}, {%0,%1,%2,%3};"
        : "+f"(c[0]), "+f"(c[1]), "+f"(c[2]), "+f"(c[3])
        : "r"(a[0]), "r"(a[1]), "r"(a[2]), "r"(a[3]), "r"(b[0]), "r"(b[1]));
}

// truncate-split: hi = bf16 truncation of v (exact), lo = bf16_rn(v - hi).
// Packs two values: hi_pair/lo_pair are bf16x2 (v0 in low half).
__device__ __forceinline__ void split2(float v0, float v1,
                                       uint32_t& hi_pair, uint32_t& lo_pair) {
    uint32_t b0 = __float_as_uint(v0) & 0xFFFF0000u;
    uint32_t b1 = __float_as_uint(v1) & 0xFFFF0000u;
    hi_pair = __byte_perm(b0, b1, 0x7632);
    float l0 = v0 - __uint_as_float(b0);
    float l1 = v1 - __uint_as_float(b1);
    __nv_bfloat162 p = __floats2bfloat162_rn(l0, l1);
    lo_pair = *reinterpret_cast<uint32_t*>(&p);
}

__device__ __forceinline__ uint32_t pack_bf16(float v0, float v1) {
    __nv_bfloat162 p = __floats2bfloat162_rn(v0, v1);
    return *reinterpret_cast<uint32_t*>(&p);
}

// ---------------------------------------------------------------------------
// Kernel 1: xa[m, r] = SCALING * sum_k x[m,k] * lora_A[r,k]   (256 x 16)
// ---------------------------------------------------------------------------
__global__ __launch_bounds__(256)
void lora_xa_kernel(const float* __restrict__ x, const float* __restrict__ loraA) {
    const int m   = blockIdx.x;
    const int tid = threadIdx.x;
    const int lid = tid & 31;
    const int wid = tid >> 5;

    float acc[R_DIM];
#pragma unroll
    for (int r = 0; r < R_DIM; r++) acc[r] = 0.f;

    const float4* x4 = reinterpret_cast<const float4*>(x + (size_t)m * K_DIM);
    const float4* a4 = reinterpret_cast<const float4*>(loraA);

#pragma unroll
    for (int i = 0; i < 4; i++) {
        int f = tid + i * 256;
        float4 xv = x4[f];
#pragma unroll
        for (int r = 0; r < R_DIM; r++) {
            float4 av = a4[r * (K_DIM / 4) + f];
            acc[r] = fmaf(xv.x, av.x, acc[r]);
            acc[r] = fmaf(xv.y, av.y, acc[r]);
            acc[r] = fmaf(xv.z, av.z, acc[r]);
            acc[r] = fmaf(xv.w, av.w, acc[r]);
        }
    }

#pragma unroll
    for (int r = 0; r < R_DIM; r++) {
#pragma unroll
        for (int o = 16; o > 0; o >>= 1)
            acc[r] += __shfl_xor_sync(0xFFFFFFFFu, acc[r], o);
    }

    __shared__ float red[8][R_DIM];
    if (lid == 0) {
#pragma unroll
        for (int r = 0; r < R_DIM; r++) red[wid][r] = acc[r];
    }
    __syncthreads();
    if (tid < R_DIM) {
        float v = 0.f;
#pragma unroll
        for (int w = 0; w < 8; w++) v += red[w][tid];
        g_xa[m * R_DIM + tid] = v * SCALING;
    }
}

// ---------------------------------------------------------------------------
// Kernel 2: mma.sync bf16 GEMM with 3-way split + fused LoRA step.
//   D = x_hi*w_hi + x_lo*w_hi + x_hi*w_lo  (+ xa @ loraB^T)
// 256 threads = 8 warps as 2(m) x 4(n); warp tile 64x32; 4x4 m16n8k16 frags.
// ---------------------------------------------------------------------------
__global__ __launch_bounds__(256, 1)
void gptq_lora_mma(const float* __restrict__ x,
                   const int*   __restrict__ qw,
                   const float* __restrict__ scales,
                   const int*   __restrict__ zeros,
                   const float* __restrict__ loraB,
                   float*       __restrict__ out) {
    extern __shared__ __align__(16) char sm[];
    const uint32_t sb = smem_u32(sm);

    const int tid  = threadIdx.x;
    const int lane = tid & 31;
    const int wid  = tid >> 5;
    const int m0   = blockIdx.x * BM;   // 2 m-tiles
    const int n0   = blockIdx.y * BN;   // 86 n-tiles

    // ---- fill LoRA tiles once (bf16, [128][16], pitch 32B) ----
    {
        const int row = tid & 127;
        const float* src = (tid < 128)
            ? (g_xa + (size_t)(m0 + row) * R_DIM)
            : (loraB + (size_t)(n0 + row) * R_DIM);
        char* dst = sm + ((tid < 128) ? SXA : SLB) + row * 32;
        float4 v0 = reinterpret_cast<const float4*>(src)[0];
        float4 v1 = reinterpret_cast<const float4*>(src)[1];
        float4 v2 = reinterpret_cast<const float4*>(src)[2];
        float4 v3 = reinterpret_cast<const float4*>(src)[3];
        uint4 p0 = make_uint4(pack_bf16(v0.x, v0.y), pack_bf16(v0.z, v0.w),
                              pack_bf16(v1.x, v1.y), pack_bf16(v1.z, v1.w));
        uint4 p1 = make_uint4(pack_bf16(v2.x, v2.y), pack_bf16(v2.z, v2.w),
                              pack_bf16(v3.x, v3.y), pack_bf16(v3.z, v3.w));
        *reinterpret_cast<uint4*>(dst)      = p0;
        *reinterpret_cast<uint4*>(dst + 16) = p1;
    }

    // ---- loader-thread constants: each thread owns one (row, 16-k-half) ----
    const int lrow = tid >> 1;                 // 0..127
    const int lkh  = (tid & 1) << 4;           // 0 or 16 (k elements)
    const float* aptr = x  + (size_t)(m0 + lrow) * K_DIM + lkh;
    const int*   bptr = qw + (size_t)(n0 + lrow) * K_DIM + lkh;
    const int    sgrow = (n0 + lrow) * G_DIM;
    const int    soff  = lrow * PITCH + lkh * 2;   // byte offset in tile
    char* stAhi = sm + SA_HI + soff;
    char* stAlo = sm + SA_LO + soff;
    char* stBhi = sm + SB_HI + soff;
    char* stBlo = sm + SB_LO + soff;

    // prefetch iter 0
    float4 fa[4]; int4 qb[4]; float sc, nz;
#pragma unroll
    for (int j = 0; j < 4; j++) {
        fa[j] = *reinterpret_cast<const float4*>(aptr + j * 4);
        qb[j] = *reinterpret_cast<const int4*>(bptr + j * 4);
    }
    sc = scales[sgrow];
    nz = -(float)zeros[sgrow] * sc;

    // ---- accumulators + per-warp ldmatrix lane offsets ----
    float acc[4][4][4];
#pragma unroll
    for (int mi = 0; mi < 4; mi++)
#pragma unroll
        for (int ni = 0; ni < 4; ni++)
#pragma unroll
            for (int j = 0; j < 4; j++) acc[mi][ni][j] = 0.f;

    const int wm = (wid >> 2) * 64;            // warp m offset (0/64)
    const int wn = (wid & 3) * 32;             // warp n offset (0/32/64/96)
    // A x4: lanes 0-15 -> rows 0-15 @k0, lanes 16-31 -> rows 0-15 @k+8
    const uint32_t aoff = (uint32_t)((wm + (lane & 15)) * PITCH + ((lane >> 4) << 4));
    // B x2: lanes 0-7 -> n rows @k0, lanes 8-15 -> n rows @k+8
    const uint32_t boff = (uint32_t)((wn + (lane & 7)) * PITCH + (((lane >> 3) & 1) << 4));

    for (int kt = 0; kt < KT; kt++) {
        __syncthreads();   // previous compute done -> tiles reusable

        // ---- STS with dequant + hi/lo split ----
        {
            uint32_t h[8], l[8];
#pragma unroll
            for (int j = 0; j < 4; j++) {
                split2(fa[j].x, fa[j].y, h[2 * j], l[2 * j]);
                split2(fa[j].z, fa[j].w, h[2 * j + 1], l[2 * j + 1]);
            }
            *reinterpret_cast<uint4*>(stAhi)      = make_uint4(h[0], h[1], h[2], h[3]);
            *reinterpret_cast<uint4*>(stAhi + 16) = make_uint4(h[4], h[5], h[6], h[7]);
            *reinterpret_cast<uint4*>(stAlo)      = make_uint4(l[0], l[1], l[2], l[3]);
            *reinterpret_cast<uint4*>(stAlo + 16) = make_uint4(l[4], l[5], l[6], l[7]);
#pragma unroll
            for (int j = 0; j < 4; j++) {
                float w0 = fmaf((float)qb[j].x, sc, nz);
                float w1 = fmaf((float)qb[j].y, sc, nz);
                float w2 = fmaf((float)qb[j].z, sc, nz);
                float w3 = fmaf((float)qb[j].w, sc, nz);
                split2(w0, w1, h[2 * j], l[2 * j]);
                split2(w2, w3, h[2 * j + 1], l[2 * j + 1]);
            }
            *reinterpret_cast<uint4*>(stBhi)      = make_uint4(h[0], h[1], h[2], h[3]);
            *reinterpret_cast<uint4*>(stBhi + 16) = make_uint4(h[4], h[5], h[6], h[7]);
            *reinterpret_cast<uint4*>(stBlo)      = make_uint4(l[0], l[1], l[2], l[3]);
            *reinterpret_cast<uint4*>(stBlo + 16) = make_uint4(l[4], l[5], l[6], l[7]);
        }
        __syncthreads();

        // ---- prefetch next tile into registers (hidden by MMA below) ----
        if (kt + 1 < KT) {
            const int k0n = (kt + 1) * BK;
#pragma unroll
            for (int j = 0; j < 4; j++) {
                fa[j] = *reinterpret_cast<const float4*>(aptr + k0n + j * 4);
                qb[j] = *reinterpret_cast<const int4*>(bptr + k0n + j * 4);
            }
            const int g = k0n >> 7;
            sc = scales[sgrow + g];
            nz = -(float)zeros[sgrow + g] * sc;
        }

        // ---- compute: 2 k16 steps x (hi*hi + hi*lo + lo*hi) = 96 MMA/warp ----
#pragma unroll
        for (int kk2 = 0; kk2 < 2; kk2++) {
            const uint32_t kb = (uint32_t)(kk2 * 32);   // 16 k-elems * 2B
            uint32_t ah[4][4], al[4][4], bh[4][2], bl[4][2];
#pragma unroll
            for (int mi = 0; mi < 4; mi++)
                ldsm_x4(sb + SA_HI + aoff + mi * (16 * PITCH) + kb, ah[mi]);
#pragma unroll
            for (int ni = 0; ni < 4; ni++)
                ldsm_x2(sb + SB_HI + boff + ni * (8 * PITCH) + kb, bh[ni]);
#pragma unroll
            for (int mi = 0; mi < 4; mi++)
#pragma unroll
                for (int ni = 0; ni < 4; ni++)
                    mma_bf16(acc[mi][ni], ah[mi], bh[ni]);
#pragma unroll
            for (int ni = 0; ni < 4; ni++)
                ldsm_x2(sb + SB_LO + boff + ni * (8 * PITCH) + kb, bl[ni]);
#pragma unroll
            for (int mi = 0; mi < 4; mi++)
#pragma unroll
                for (int ni = 0; ni < 4; ni++)
                    mma_bf16(acc[mi][ni], ah[mi], bl[ni]);
#pragma unroll
            for (int mi = 0; mi < 4; mi++)
                ldsm_x4(sb + SA_LO + aoff + mi * (16 * PITCH) + kb, al[mi]);
#pragma unroll
            for (int mi = 0; mi < 4; mi++)
#pragma unroll
                for (int ni = 0; ni < 4; ni++)
                    mma_bf16(acc[mi][ni], al[mi], bh[ni]);
        }
    }

    // ---- LoRA: one extra k16 step from the bf16 lora tiles ----
    {
        const uint32_t aoffL = (uint32_t)((wm + (lane & 15)) * 32 + ((lane >> 4) << 4));
        const uint32_t boffL = (uint32_t)((wn + (lane & 7)) * 32 + (((lane >> 3) & 1) << 4));
        uint32_t ah[4][4], bh[4][2];
#pragma unroll
        for (int mi = 0; mi < 4; mi++)
            ldsm_x4(sb + SXA + aoffL + mi * (16 * 32), ah[mi]);
#pragma unroll
        for (int ni = 0; ni < 4; ni++)
            ldsm_x2(sb + SLB + boffL + ni * (8 * 32), bh[ni]);
#pragma unroll
        for (int mi = 0; mi < 4; mi++)
#pragma unroll
            for (int ni = 0; ni < 4; ni++)
                mma_bf16(acc[mi][ni], ah[mi], bh[ni]);
    }

    // ---- store: c-frag lane layout -> gmem float2 writes ----
    {
        const int r  = lane >> 2;
        const int c2 = (lane & 3) * 2;
#pragma unroll
        for (int mi = 0; mi < 4; mi++) {
#pragma unroll
            for (int ni = 0; ni < 4; ni++) {
                const int m = m0 + wm + mi * 16 + r;
                const int n = n0 + wn + ni * 8 + c2;
                float* p = out + (size_t)m * N_DIM + n;
                *reinterpret_cast<float2*>(p) =
                    make_float2(acc[mi][ni][0], acc[mi][ni][1]);
                *reinterpret_cast<float2*>(p + 8 * (size_t)N_DIM) =
                    make_float2(acc[mi][ni][2], acc[mi][ni][3]);
            }
        }
    }
}

// ---------------------------------------------------------------------------
// kernel_launch — inputs: x, qweight, scales, zeros, lora_A, lora_B
// ---------------------------------------------------------------------------
extern "C" void kernel_launch(void* const* d_in, const int* in_sizes, int n_in,
                              void* d_out, int out_size) {
    const float* x      = (const float*)d_in[0];
    const int*   qw     = (const int*)  d_in[1];
    const float* scales = (const float*)d_in[2];
    const int*   zeros  = (const int*)  d_in[3];
    const float* loraA  = (const float*)d_in[4];
    const float* loraB  = (const float*)d_in[5];
    float*       out    = (float*)d_out;

    cudaFuncSetAttribute(gptq_lora_mma,
                         cudaFuncAttributeMaxDynamicSharedMemorySize, SMEM_BYTES);

    lora_xa_kernel<<<M_DIM, 256>>>(x, loraA);

    dim3 grid(M_DIM / BM, N_DIM / BN);   // (2, 86): m-pairs adjacent -> qweight L2 reuse
    gptq_lora_mma<<<grid, 256, SMEM_BYTES>>>(x, qw, scales, zeros, loraB, out);
}

// round 4
// speedup vs baseline: 3.3137x; 1.5288x over previous
#include <cuda_runtime.h>
#include <cuda_bf16.h>
#include <cstdint>

// ---------------------------------------------------------------------------
// Problem constants
// ---------------------------------------------------------------------------
#define M_DIM 256
#define K_DIM 4096
#define N_DIM 11008
#define G_DIM 32
#define R_DIM 16
#define SCALING 2.0f

#define BM 64
#define BN 128
#define BK 32
#define KT (K_DIM / BK)     // 128

// SMEM layout (dynamic). A tiles: [64][32] bf16, pitch 80B. B: [128][32] bf16, pitch 80B.
#define PITCH   80
#define A_STAGE 10240        // AH(5120) + AL(5120)
#define A_LO    5120
#define B_BASE  30720        // after 3 A stages
#define B_STAGE 10240
#define SXA     51200        // lora xa tile [64][16] bf16, pitch 32
#define SLB     53248        // lora B tile [128][16] bf16, pitch 32
#define SMEM_BYTES 57344

// Global scratch (__device__ arrays: allowed; no runtime alloc)
__device__ __align__(16) float g_xa[M_DIM * R_DIM];
__device__ __align__(16) __nv_bfloat16 g_xhi[M_DIM * K_DIM];
__device__ __align__(16) __nv_bfloat16 g_xlo[M_DIM * K_DIM];

// ---------------------------------------------------------------------------
// helpers (family-common PTX only)
// ---------------------------------------------------------------------------
__device__ __forceinline__ uint32_t smem_u32(const void* p) {
    uint32_t a;
    asm("{ .reg .u64 t; cvta.to.shared.u64 t, %1; cvt.u32.u64 %0, t; }"
        : "=r"(a) : "l"(p));
    return a;
}
__device__ __forceinline__ void ldsm_x4(uint32_t addr, uint32_t* r) {
    asm volatile("ldmatrix.sync.aligned.m8n8.x4.shared.b16 {%0,%1,%2,%3}, [%4];"
                 : "=r"(r[0]), "=r"(r[1]), "=r"(r[2]), "=r"(r[3]) : "r"(addr));
}
__device__ __forceinline__ void ldsm_x2(uint32_t addr, uint32_t* r) {
    asm volatile("ldmatrix.sync.aligned.m8n8.x2.shared.b16 {%0,%1}, [%2];"
                 : "=r"(r[0]), "=r"(r[1]) : "r"(addr));
}
__device__ __forceinline__ void mma_bf16(float* c, const uint32_t* a, const uint32_t* b) {
    asm volatile(
        "mma.sync.aligned.m16n8k16.row.col.f32.bf16.bf16.f32 "
        "{%0,%1,%2,%3}, {%4,%5,%6,%7}, {%8,%9}, {%0,%1,%2,%3};"
        : "+f"(c[0]), "+f"(c[1]), "+f"(c[2]), "+f"(c[3])
        : "r"(a[0]), "r"(a[1]), "r"(a[2]), "r"(a[3]), "r"(b[0]), "r"(b[1]));
}
__device__ __forceinline__ void cpa16(uint32_t dst, const void* src) {
    asm volatile("cp.async.cg.shared.global [%0], [%1], 16;"
                 :: "r"(dst), "l"(src) : "memory");
}
__device__ __forceinline__ void cpa_commit() {
    asm volatile("cp.async.commit_group;" ::: "memory");
}
__device__ __forceinline__ void cpa_wait1() {
    asm volatile("cp.async.wait_group 1;" ::: "memory");
}

__device__ __forceinline__ uint32_t pack_bf16(float v0, float v1) {
    __nv_bfloat162 p = __floats2bfloat162_rn(v0, v1);
    return *reinterpret_cast<uint32_t*>(&p);
}
// hi = bf16 truncation of v (exact), lo = bf16_rn(v - hi)
__device__ __forceinline__ void split2(float v0, float v1,
                                       uint32_t& hi_pair, uint32_t& lo_pair) {
    uint32_t b0 = __float_as_uint(v0) & 0xFFFF0000u;
    uint32_t b1 = __float_as_uint(v1) & 0xFFFF0000u;
    hi_pair = __byte_perm(b0, b1, 0x7632);
    lo_pair = pack_bf16(v0 - __uint_as_float(b0), v1 - __uint_as_float(b1));
}

// ---------------------------------------------------------------------------
// Kernel 0: pre-split x into bf16 hi/lo (read once, reused by 86 n-tiles)
// ---------------------------------------------------------------------------
__global__ __launch_bounds__(256)
void xsplit_kernel(const float* __restrict__ x) {
    const int i4 = blockIdx.x * 256 + threadIdx.x;   // handles 4 floats
    float4 v = reinterpret_cast<const float4*>(x)[i4];
    uint32_t h0, l0, h1, l1;
    split2(v.x, v.y, h0, l0);
    split2(v.z, v.w, h1, l1);
    reinterpret_cast<uint2*>(g_xhi)[i4] = make_uint2(h0, h1);
    reinterpret_cast<uint2*>(g_xlo)[i4] = make_uint2(l0, l1);
}

// ---------------------------------------------------------------------------
// Kernel 1: xa[m, r] = SCALING * sum_k x[m,k] * lora_A[r,k]
// ---------------------------------------------------------------------------
__global__ __launch_bounds__(256)
void lora_xa_kernel(const float* __restrict__ x, const float* __restrict__ loraA) {
    const int m   = blockIdx.x;
    const int tid = threadIdx.x;
    const int lid = tid & 31;
    const int wid = tid >> 5;

    float acc[R_DIM];
#pragma unroll
    for (int r = 0; r < R_DIM; r++) acc[r] = 0.f;

    const float4* x4 = reinterpret_cast<const float4*>(x + (size_t)m * K_DIM);
    const float4* a4 = reinterpret_cast<const float4*>(loraA);

#pragma unroll
    for (int i = 0; i < 4; i++) {
        int f = tid + i * 256;
        float4 xv = x4[f];
#pragma unroll
        for (int r = 0; r < R_DIM; r++) {
            float4 av = a4[r * (K_DIM / 4) + f];
            acc[r] = fmaf(xv.x, av.x, acc[r]);
            acc[r] = fmaf(xv.y, av.y, acc[r]);
            acc[r] = fmaf(xv.z, av.z, acc[r]);
            acc[r] = fmaf(xv.w, av.w, acc[r]);
        }
    }
#pragma unroll
    for (int r = 0; r < R_DIM; r++) {
#pragma unroll
        for (int o = 16; o > 0; o >>= 1)
            acc[r] += __shfl_xor_sync(0xFFFFFFFFu, acc[r], o);
    }
    __shared__ float red[8][R_DIM];
    if (lid == 0) {
#pragma unroll
        for (int r = 0; r < R_DIM; r++) red[wid][r] = acc[r];
    }
    __syncthreads();
    if (tid < R_DIM) {
        float v = 0.f;
#pragma unroll
        for (int w = 0; w < 8; w++) v += red[w][tid];
        g_xa[m * R_DIM + tid] = v * SCALING;
    }
}

// ---------------------------------------------------------------------------
// Kernel 2: GEMM. partial = sum_{k in group} (x_hi + x_lo) * (q - z)  [bf16 MMA]
//           total  += s[n,g] * partial per group; + LoRA k16 step.
// 256 threads = 8 warps 2(m) x 4(n); warp tile 32x128/4 = 32x32; 2 CTAs/SM.
// Pipeline: A via cp.async (3-stage ring), B via LDG->dequant->STS (2-stage),
// one __syncthreads per iteration.
// ---------------------------------------------------------------------------
__global__ __launch_bounds__(256, 2)
void gptq_lora_mma(const int*   __restrict__ qw,
                   const float* __restrict__ scales,
                   const int*   __restrict__ zeros,
                   const float* __restrict__ loraB,
                   float*       __restrict__ out) {
    extern __shared__ __align__(16) char sm[];
    const uint32_t sb = smem_u32(sm);

    const int tid  = threadIdx.x;
    const int lane = tid & 31;
    const int wid  = tid >> 5;
    const int m0   = blockIdx.x * BM;    // 4 m-tiles
    const int n0   = blockIdx.y * BN;    // 86 n-tiles

    // ---- LoRA tiles (once) ----
    if (tid < 192) {
        const int row = (tid < 64) ? tid : (tid - 64);
        const float* src = (tid < 64)
            ? (g_xa + (size_t)(m0 + row) * R_DIM)
            : (loraB + (size_t)(n0 + row) * R_DIM);
        char* dst = sm + ((tid < 64) ? SXA : SLB) + row * 32;
        float4 v0 = reinterpret_cast<const float4*>(src)[0];
        float4 v1 = reinterpret_cast<const float4*>(src)[1];
        float4 v2 = reinterpret_cast<const float4*>(src)[2];
        float4 v3 = reinterpret_cast<const float4*>(src)[3];
        *reinterpret_cast<uint4*>(dst) =
            make_uint4(pack_bf16(v0.x, v0.y), pack_bf16(v0.z, v0.w),
                       pack_bf16(v1.x, v1.y), pack_bf16(v1.z, v1.w));
        *reinterpret_cast<uint4*>(dst + 16) =
            make_uint4(pack_bf16(v2.x, v2.y), pack_bf16(v2.z, v2.w),
                       pack_bf16(v3.x, v3.y), pack_bf16(v3.z, v3.w));
    }

    // ---- loader thread mapping ----
    // A: 64 rows x 4 chunks(16B) per matrix; 1 chunk per thread per matrix.
    const int arow = tid >> 2;
    const int achk = tid & 3;
    const __nv_bfloat16* agm_hi = g_xhi + (size_t)(m0 + arow) * K_DIM + achk * 8;
    const __nv_bfloat16* agm_lo = g_xlo + (size_t)(m0 + arow) * K_DIM + achk * 8;
    const uint32_t a_soff = (uint32_t)(arow * PITCH + achk * 16);
    // B: 128 rows x 32 ints; 16 ints (half row) per thread.
    const int brow = tid >> 1;
    const int bkh  = (tid & 1) * 16;
    const int* bgm = qw + (size_t)(n0 + brow) * K_DIM + bkh;
    const int  zro = (n0 + brow) * G_DIM;
    const uint32_t b_soff = (uint32_t)(brow * PITCH + bkh * 2);
    char* const bsm0 = sm + B_BASE + b_soff;
    char* const bsm1 = sm + B_BASE + B_STAGE + b_soff;

    // ---- prologue ----
    cpa16(sb + 0 * A_STAGE + a_soff, agm_hi);
    cpa16(sb + 0 * A_STAGE + A_LO + a_soff, agm_lo);
    cpa_commit();
    cpa16(sb + 1 * A_STAGE + a_soff, agm_hi + 32);
    cpa16(sb + 1 * A_STAGE + A_LO + a_soff, agm_lo + 32);
    cpa_commit();

    int4 qb[4];
    int  zi;
    // B(0): blocking load + STS
    {
#pragma unroll
        for (int j = 0; j < 4; j++) qb[j] = reinterpret_cast<const int4*>(bgm)[j];
        zi = zeros[zro];
        uint32_t o[8];
#pragma unroll
        for (int j = 0; j < 4; j++) {
            o[2 * j]     = pack_bf16((float)(qb[j].x - zi), (float)(qb[j].y - zi));
            o[2 * j + 1] = pack_bf16((float)(qb[j].z - zi), (float)(qb[j].w - zi));
        }
        *reinterpret_cast<uint4*>(bsm0)      = make_uint4(o[0], o[1], o[2], o[3]);
        *reinterpret_cast<uint4*>(bsm0 + 16) = make_uint4(o[4], o[5], o[6], o[7]);
    }
    // B(1) -> regs
#pragma unroll
    for (int j = 0; j < 4; j++)
        qb[j] = reinterpret_cast<const int4*>(bgm + 32)[j];
    zi = zeros[zro];   // (1)>>2 == 0

    cpa_wait1();
    __syncthreads();

    // ---- accumulators ----
    float tac[2][4][4], pac[2][4][4];
#pragma unroll
    for (int mi = 0; mi < 2; mi++)
#pragma unroll
        for (int ni = 0; ni < 4; ni++)
#pragma unroll
            for (int j = 0; j < 4; j++) { tac[mi][ni][j] = 0.f; pac[mi][ni][j] = 0.f; }

    const int wm = (wid >> 2) * 32;
    const int wn = (wid & 3) * 32;
    const uint32_t aoff = (uint32_t)((wm + (lane & 15)) * PITCH + ((lane >> 4) << 4));
    const uint32_t boff = (uint32_t)((wn + (lane & 7)) * PITCH + (((lane >> 3) & 1) << 4));
    const float* scp = scales + (size_t)(n0 + wn + (lane & 3) * 2) * G_DIM;

    int csA = 0, nsA = 2;   // compute A-stage, cp.async dest A-stage

    for (int kt = 0; kt < KT; kt++) {
        // 1. STS B(kt+1) into B-stage (kt+1)&1
        if (kt < KT - 1) {
            char* bd = ((kt + 1) & 1) ? bsm1 : bsm0;
            uint32_t o[8];
#pragma unroll
            for (int j = 0; j < 4; j++) {
                o[2 * j]     = pack_bf16((float)(qb[j].x - zi), (float)(qb[j].y - zi));
                o[2 * j + 1] = pack_bf16((float)(qb[j].z - zi), (float)(qb[j].w - zi));
            }
            *reinterpret_cast<uint4*>(bd)      = make_uint4(o[0], o[1], o[2], o[3]);
            *reinterpret_cast<uint4*>(bd + 16) = make_uint4(o[4], o[5], o[6], o[7]);
        }
        // 2. prefetch kt+2: cp.async A, LDG B
        if (kt < KT - 2) {
            const int kn = kt + 2;
            cpa16(sb + nsA * A_STAGE + a_soff, agm_hi + kn * 32);
            cpa16(sb + nsA * A_STAGE + A_LO + a_soff, agm_lo + kn * 32);
#pragma unroll
            for (int j = 0; j < 4; j++)
                qb[j] = reinterpret_cast<const int4*>(bgm + kn * 32)[j];
            zi = zeros[zro + (kn >> 2)];
        }
        cpa_commit();   // always: keeps group indices uniform

        // 3. compute stage (A: csA, B: kt&1)
        {
            const uint32_t Ab = sb + csA * A_STAGE;
            const uint32_t Bb = sb + B_BASE + (uint32_t)((kt & 1) * B_STAGE);
#pragma unroll
            for (int kk = 0; kk < 2; kk++) {
                const uint32_t kb = (uint32_t)(kk * 32);
                uint32_t ah[2][4], al[2][4], b[4][2];
#pragma unroll
                for (int mi = 0; mi < 2; mi++) {
                    ldsm_x4(Ab + aoff + mi * (16 * PITCH) + kb, ah[mi]);
                    ldsm_x4(Ab + A_LO + aoff + mi * (16 * PITCH) + kb, al[mi]);
                }
#pragma unroll
                for (int ni = 0; ni < 4; ni++)
                    ldsm_x2(Bb + boff + ni * (8 * PITCH) + kb, b[ni]);
#pragma unroll
                for (int mi = 0; mi < 2; mi++)
#pragma unroll
                    for (int ni = 0; ni < 4; ni++) {
                        mma_bf16(pac[mi][ni], ah[mi], b[ni]);
                        mma_bf16(pac[mi][ni], al[mi], b[ni]);
                    }
            }
        }

        // 4. group rescale: total += s[n,g] * partial
        if ((kt & 3) == 3) {
            const int g = kt >> 2;
#pragma unroll
            for (int ni = 0; ni < 4; ni++) {
                float s0 = scp[ni * 8 * G_DIM + g];
                float s1 = scp[ni * 8 * G_DIM + G_DIM + g];
#pragma unroll
                for (int mi = 0; mi < 2; mi++) {
                    tac[mi][ni][0] = fmaf(pac[mi][ni][0], s0, tac[mi][ni][0]);
                    tac[mi][ni][1] = fmaf(pac[mi][ni][1], s1, tac[mi][ni][1]);
                    tac[mi][ni][2] = fmaf(pac[mi][ni][2], s0, tac[mi][ni][2]);
                    tac[mi][ni][3] = fmaf(pac[mi][ni][3], s1, tac[mi][ni][3]);
                    pac[mi][ni][0] = 0.f; pac[mi][ni][1] = 0.f;
                    pac[mi][ni][2] = 0.f; pac[mi][ni][3] = 0.f;
                }
            }
        }

        cpa_wait1();
        __syncthreads();
        csA = (csA == 2) ? 0 : csA + 1;
        nsA = (nsA == 2) ? 0 : nsA + 1;
    }

    // ---- LoRA k16 step (pac is zero after final rescale) ----
    {
        uint32_t ah[2][4], b[4][2];
#pragma unroll
        for (int mi = 0; mi < 2; mi++)
            ldsm_x4(sb + SXA + (uint32_t)((wm + mi * 16 + (lane & 15)) * 32 + ((lane >> 4) << 4)), ah[mi]);
#pragma unroll
        for (int ni = 0; ni < 4; ni++)
            ldsm_x2(sb + SLB + (uint32_t)((wn + ni * 8 + (lane & 7)) * 32 + (((lane >> 3) & 1) << 4)), b[ni]);
#pragma unroll
        for (int mi = 0; mi < 2; mi++)
#pragma unroll
            for (int ni = 0; ni < 4; ni++) {
                mma_bf16(pac[mi][ni], ah[mi], b[ni]);
#pragma unroll
                for (int j = 0; j < 4; j++)
                    tac[mi][ni][j] += pac[mi][ni][j];
            }
    }

    // ---- store ----
    {
        const int r  = lane >> 2;
        const int c2 = (lane & 3) * 2;
#pragma unroll
        for (int mi = 0; mi < 2; mi++) {
#pragma unroll
            for (int ni = 0; ni < 4; ni++) {
                const int m = m0 + wm + mi * 16 + r;
                const int n = n0 + wn + ni * 8 + c2;
                float* p = out + (size_t)m * N_DIM + n;
                *reinterpret_cast<float2*>(p) =
                    make_float2(tac[mi][ni][0], tac[mi][ni][1]);
                *reinterpret_cast<float2*>(p + 8 * (size_t)N_DIM) =
                    make_float2(tac[mi][ni][2], tac[mi][ni][3]);
            }
        }
    }
}

// ---------------------------------------------------------------------------
// kernel_launch — inputs: x, qweight, scales, zeros, lora_A, lora_B
// ---------------------------------------------------------------------------
extern "C" void kernel_launch(void* const* d_in, const int* in_sizes, int n_in,
                              void* d_out, int out_size) {
    const float* x      = (const float*)d_in[0];
    const int*   qw     = (const int*)  d_in[1];
    const float* scales = (const float*)d_in[2];
    const int*   zeros  = (const int*)  d_in[3];
    const float* loraA  = (const float*)d_in[4];
    const float* loraB  = (const float*)d_in[5];
    float*       out    = (float*)d_out;

    cudaFuncSetAttribute(gptq_lora_mma,
                         cudaFuncAttributeMaxDynamicSharedMemorySize, SMEM_BYTES);

    xsplit_kernel<<<(M_DIM * K_DIM) / (256 * 4), 256>>>(x);
    lora_xa_kernel<<<M_DIM, 256>>>(x, loraA);

    dim3 grid(M_DIM / BM, N_DIM / BN);   // (4, 86): m fastest -> qweight L2 dedup
    gptq_lora_mma<<<grid, 256, SMEM_BYTES>>>(qw, scales, zeros, loraB, out);
}

// round 6
// speedup vs baseline: 3.8491x; 1.1616x over previous
#include <cuda_runtime.h>
#include <cuda_bf16.h>
#include <cstdint>

// ---------------------------------------------------------------------------
// Problem constants
// ---------------------------------------------------------------------------
#define M_DIM 256
#define K_DIM 4096
#define N_DIM 11008
#define G_DIM 32
#define R_DIM 16
#define SCALING 2.0f

#define BM 64
#define BN 128
#define BK 64
#define KT (K_DIM / BK)     // 64

// SMEM layout. A tiles: [64 rows][64 k] bf16, pitch 144B (hi + lo per stage).
// B tiles: [128 rows][64 k] bf16, pitch 144B.
#define PITCH   144
#define A_STAGE 18432        // 64*144 (hi) + 64*144 (lo) -> 2*9216
#define A_LO    9216
#define B_BASE  55296        // after 3 A stages
#define B_STAGE 18432        // 128*144
#define SXA     92160        // lora xa tile [64][16] bf16, pitch 32
#define SLB     94208        // lora B tile [128][16] bf16, pitch 32
#define SMEM_BYTES 98304

// Global scratch (__device__ arrays: no runtime alloc)
__device__ __align__(16) float g_xa[M_DIM * R_DIM];
__device__ __align__(16) __nv_bfloat16 g_xhi[M_DIM * K_DIM];
__device__ __align__(16) __nv_bfloat16 g_xlo[M_DIM * K_DIM];
__device__ __align__(16) char g_qw8[(size_t)N_DIM * K_DIM];   // w8 = q - z, [-15,15]

// ---------------------------------------------------------------------------
// helpers (family-common PTX only)
// ---------------------------------------------------------------------------
__device__ __forceinline__ uint32_t smem_u32(const void* p) {
    uint32_t a;
    asm("{ .reg .u64 t; cvta.to.shared.u64 t, %1; cvt.u32.u64 %0, t; }"
        : "=r"(a) : "l"(p));
    return a;
}
__device__ __forceinline__ void ldsm_x4(uint32_t addr, uint32_t* r) {
    asm volatile("ldmatrix.sync.aligned.m8n8.x4.shared.b16 {%0,%1,%2,%3}, [%4];"
                 : "=r"(r[0]), "=r"(r[1]), "=r"(r[2]), "=r"(r[3]) : "r"(addr));
}
__device__ __forceinline__ void ldsm_x2(uint32_t addr, uint32_t* r) {
    asm volatile("ldmatrix.sync.aligned.m8n8.x2.shared.b16 {%0,%1}, [%2];"
                 : "=r"(r[0]), "=r"(r[1]) : "r"(addr));
}
__device__ __forceinline__ void mma_bf16(float* c, const uint32_t* a, const uint32_t* b) {
    asm volatile(
        "mma.sync.aligned.m16n8k16.row.col.f32.bf16.bf16.f32 "
        "{%0,%1,%2,%3}, {%4,%5,%6,%7}, {%8,%9}, {%0,%1,%2,%3};"
        : "+f"(c[0]), "+f"(c[1]), "+f"(c[2]), "+f"(c[3])
        : "r"(a[0]), "r"(a[1]), "r"(a[2]), "r"(a[3]), "r"(b[0]), "r"(b[1]));
}
__device__ __forceinline__ void cpa16(uint32_t dst, const void* src) {
    asm volatile("cp.async.cg.shared.global [%0], [%1], 16;"
                 :: "r"(dst), "l"(src) : "memory");
}
__device__ __forceinline__ void cpa_commit() {
    asm volatile("cp.async.commit_group;" ::: "memory");
}
__device__ __forceinline__ void cpa_wait1() {
    asm volatile("cp.async.wait_group 1;" ::: "memory");
}
__device__ __forceinline__ uint32_t pack_bf16(float v0, float v1) {
    __nv_bfloat162 p = __floats2bfloat162_rn(v0, v1);
    return *reinterpret_cast<uint32_t*>(&p);
}
// hi = bf16 truncation of v (exact), lo = bf16_rn(v - hi)
__device__ __forceinline__ void split2(float v0, float v1,
                                       uint32_t& hi_pair, uint32_t& lo_pair) {
    uint32_t b0 = __float_as_uint(v0) & 0xFFFF0000u;
    uint32_t b1 = __float_as_uint(v1) & 0xFFFF0000u;
    hi_pair = __byte_perm(b0, b1, 0x7632);
    lo_pair = pack_bf16(v0 - __uint_as_float(b0), v1 - __uint_as_float(b1));
}
// 4 signed int8 (packed u32) -> 2 bf16x2 words (exact: values in [-15,15])
__device__ __forceinline__ void dq8(uint32_t w, uint32_t& p0, uint32_t& p1) {
    int b0 = __dp4a((int)w, 0x00000001, 0);
    int b1 = __dp4a((int)w, 0x00000100, 0);
    int b2 = __dp4a((int)w, 0x00010000, 0);
    int b3 = __dp4a((int)w, 0x01000000, 0);
    p0 = pack_bf16((float)b0, (float)b1);
    p1 = pack_bf16((float)b2, (float)b3);
}

// ---------------------------------------------------------------------------
// Kernel 0a: split x into bf16 hi/lo
// ---------------------------------------------------------------------------
__global__ __launch_bounds__(256)
void xsplit_kernel(const float* __restrict__ x) {
    const int i4 = blockIdx.x * 256 + threadIdx.x;
    float4 v = reinterpret_cast<const float4*>(x)[i4];
    uint32_t h0, l0, h1, l1;
    split2(v.x, v.y, h0, l0);
    split2(v.z, v.w, h1, l1);
    reinterpret_cast<uint2*>(g_xhi)[i4] = make_uint2(h0, h1);
    reinterpret_cast<uint2*>(g_xlo)[i4] = make_uint2(l0, l1);
}

// ---------------------------------------------------------------------------
// Kernel 0b: pack w8 = qweight - zeros into int8 (exact, [-15,15])
// ---------------------------------------------------------------------------
__global__ __launch_bounds__(256)
void pack_qw8(const int* __restrict__ qw, const int* __restrict__ zeros) {
    const size_t base = ((size_t)blockIdx.x * 256 + threadIdx.x) * 8;
    const int o = (int)(base >> 12);          // / 4096
    const int i = (int)(base & 4095);
    const int z = zeros[o * G_DIM + (i >> 7)];
    int4 a = reinterpret_cast<const int4*>(qw + base)[0];
    int4 b = reinterpret_cast<const int4*>(qw + base)[1];
    uint32_t lo = (uint32_t)((a.x - z) & 0xFF)        |
                  ((uint32_t)((a.y - z) & 0xFF) << 8)  |
                  ((uint32_t)((a.z - z) & 0xFF) << 16) |
                  ((uint32_t)((a.w - z) & 0xFF) << 24);
    uint32_t hi = (uint32_t)((b.x - z) & 0xFF)        |
                  ((uint32_t)((b.y - z) & 0xFF) << 8)  |
                  ((uint32_t)((b.z - z) & 0xFF) << 16) |
                  ((uint32_t)((b.w - z) & 0xFF) << 24);
    *reinterpret_cast<uint2*>(g_qw8 + base) = make_uint2(lo, hi);
}

// ---------------------------------------------------------------------------
// Kernel 1: xa[m, r] = SCALING * sum_k x[m,k] * lora_A[r,k]
// ---------------------------------------------------------------------------
__global__ __launch_bounds__(256)
void lora_xa_kernel(const float* __restrict__ x, const float* __restrict__ loraA) {
    const int m   = blockIdx.x;
    const int tid = threadIdx.x;
    const int lid = tid & 31;
    const int wid = tid >> 5;

    float acc[R_DIM];
#pragma unroll
    for (int r = 0; r < R_DIM; r++) acc[r] = 0.f;

    const float4* x4 = reinterpret_cast<const float4*>(x + (size_t)m * K_DIM);
    const float4* a4 = reinterpret_cast<const float4*>(loraA);
#pragma unroll
    for (int i = 0; i < 4; i++) {
        int f = tid + i * 256;
        float4 xv = x4[f];
#pragma unroll
        for (int r = 0; r < R_DIM; r++) {
            float4 av = a4[r * (K_DIM / 4) + f];
            acc[r] = fmaf(xv.x, av.x, acc[r]);
            acc[r] = fmaf(xv.y, av.y, acc[r]);
            acc[r] = fmaf(xv.z, av.z, acc[r]);
            acc[r] = fmaf(xv.w, av.w, acc[r]);
        }
    }
#pragma unroll
    for (int r = 0; r < R_DIM; r++) {
#pragma unroll
        for (int o = 16; o > 0; o >>= 1)
            acc[r] += __shfl_xor_sync(0xFFFFFFFFu, acc[r], o);
    }
    __shared__ float red[8][R_DIM];
    if (lid == 0) {
#pragma unroll
        for (int r = 0; r < R_DIM; r++) red[wid][r] = acc[r];
    }
    __syncthreads();
    if (tid < R_DIM) {
        float v = 0.f;
#pragma unroll
        for (int w = 0; w < 8; w++) v += red[w][tid];
        g_xa[m * R_DIM + tid] = v * SCALING;
    }
}

// ---------------------------------------------------------------------------
// Kernel 2: main GEMM.
//   pac += (x_hi + x_lo) * w8 per group (bf16 MMA, exact w);
//   tac += s[n,g] * pac per group; + LoRA k16 step.
// ---------------------------------------------------------------------------
__global__ __launch_bounds__(256, 2)
void gptq_lora_mma(const float* __restrict__ scales,
                   const float* __restrict__ loraB,
                   float*       __restrict__ out) {
    extern __shared__ __align__(16) char sm[];
    const uint32_t sb = smem_u32(sm);

    const int tid  = threadIdx.x;
    const int lane = tid & 31;
    const int wid  = tid >> 5;
    const int m0   = blockIdx.x * BM;    // 4 m-tiles
    const int n0   = blockIdx.y * BN;    // 86 n-tiles

    // ---- LoRA tiles (once) ----
    if (tid < 192) {
        const int row = (tid < 64) ? tid : (tid - 64);
        const float* src = (tid < 64)
            ? (g_xa + (size_t)(m0 + row) * R_DIM)
            : (loraB + (size_t)(n0 + row) * R_DIM);
        char* dst = sm + ((tid < 64) ? SXA : SLB) + row * 32;
        float4 v0 = reinterpret_cast<const float4*>(src)[0];
        float4 v1 = reinterpret_cast<const float4*>(src)[1];
        float4 v2 = reinterpret_cast<const float4*>(src)[2];
        float4 v3 = reinterpret_cast<const float4*>(src)[3];
        *reinterpret_cast<uint4*>(dst) =
            make_uint4(pack_bf16(v0.x, v0.y), pack_bf16(v0.z, v0.w),
                       pack_bf16(v1.x, v1.y), pack_bf16(v1.z, v1.w));
        *reinterpret_cast<uint4*>(dst + 16) =
            make_uint4(pack_bf16(v2.x, v2.y), pack_bf16(v2.z, v2.w),
                       pack_bf16(v3.x, v3.y), pack_bf16(v3.z, v3.w));
    }

    // ---- loader mappings ----
    const int arow = tid >> 2;
    const int acho = (tid & 3) * 32;                       // byte offset in row
    const __nv_bfloat16* agm_hi = g_xhi + (size_t)(m0 + arow) * K_DIM + (acho >> 1);
    const __nv_bfloat16* agm_lo = g_xlo + (size_t)(m0 + arow) * K_DIM + (acho >> 1);
    const uint32_t a_soff = (uint32_t)(arow * PITCH + acho);
    const int brow = tid >> 1;
    const int bkh  = (tid & 1) * 32;                       // k offset (elems)
    const char* bgm = g_qw8 + (size_t)(n0 + brow) * K_DIM + bkh;
    const uint32_t b_soff = (uint32_t)(brow * PITCH + bkh * 2);

    // ---- prologue ----
    // A stage 0 <- A(0): k 0..63
    cpa16(sb + 0 * A_STAGE + a_soff, agm_hi);
    cpa16(sb + 0 * A_STAGE + a_soff + 16, agm_hi + 8);
    cpa16(sb + 0 * A_STAGE + A_LO + a_soff, agm_lo);
    cpa16(sb + 0 * A_STAGE + A_LO + a_soff + 16, agm_lo + 8);
    cpa_commit();
    // A stage 1 <- A(1): k 64..127   (BK=64!)
    cpa16(sb + 1 * A_STAGE + a_soff, agm_hi + 64);
    cpa16(sb + 1 * A_STAGE + a_soff + 16, agm_hi + 72);
    cpa16(sb + 1 * A_STAGE + A_LO + a_soff, agm_lo + 64);
    cpa16(sb + 1 * A_STAGE + A_LO + a_soff + 16, agm_lo + 72);
    cpa_commit();

    uint4 qb[2][2];
    // B(0): blocking LDG + dequant + STS into B stage 0
    {
        uint4 r0 = reinterpret_cast<const uint4*>(bgm)[0];
        uint4 r1 = reinterpret_cast<const uint4*>(bgm)[1];
        uint32_t o[16];
        dq8(r0.x, o[0], o[1]);  dq8(r0.y, o[2], o[3]);
        dq8(r0.z, o[4], o[5]);  dq8(r0.w, o[6], o[7]);
        dq8(r1.x, o[8], o[9]);  dq8(r1.y, o[10], o[11]);
        dq8(r1.z, o[12], o[13]); dq8(r1.w, o[14], o[15]);
        char* bd = sm + B_BASE + b_soff;
#pragma unroll
        for (int j = 0; j < 4; j++)
            reinterpret_cast<uint4*>(bd + j * 16)[0] =
                make_uint4(o[4 * j], o[4 * j + 1], o[4 * j + 2], o[4 * j + 3]);
    }
    qb[0][0] = reinterpret_cast<const uint4*>(bgm + 1 * BK)[0];
    qb[0][1] = reinterpret_cast<const uint4*>(bgm + 1 * BK)[1];
    qb[1][0] = reinterpret_cast<const uint4*>(bgm + 2 * BK)[0];
    qb[1][1] = reinterpret_cast<const uint4*>(bgm + 2 * BK)[1];

    cpa_wait1();
    __syncthreads();

    // ---- accumulators / compute mappings ----
    float tac[2][4][4], pac[2][4][4];
#pragma unroll
    for (int mi = 0; mi < 2; mi++)
#pragma unroll
        for (int ni = 0; ni < 4; ni++)
#pragma unroll
            for (int j = 0; j < 4; j++) { tac[mi][ni][j] = 0.f; pac[mi][ni][j] = 0.f; }

    const int wm = (wid >> 2) * 32;            // 0/32
    const int wn = (wid & 3) * 32;             // 0..96
    const uint32_t aoff  = (uint32_t)((wm + (lane & 15)) * PITCH + ((lane >> 4) << 4));
    const uint32_t boff4 = (uint32_t)((wn + (lane & 7) + ((lane >> 4) << 3)) * PITCH
                                      + (((lane >> 3) & 1) << 4));
    const float* scp = scales + (size_t)(n0 + wn + (lane & 3) * 2) * G_DIM;

    for (int kt = 0; kt < KT; kt++) {
        // 1. dequant + STS B(kt+1) from qb[kt&1] into B stage (kt+1)&1
        if (kt < KT - 1) {
            uint32_t o[16];
            uint4 r0 = qb[kt & 1][0], r1 = qb[kt & 1][1];
            dq8(r0.x, o[0], o[1]);  dq8(r0.y, o[2], o[3]);
            dq8(r0.z, o[4], o[5]);  dq8(r0.w, o[6], o[7]);
            dq8(r1.x, o[8], o[9]);  dq8(r1.y, o[10], o[11]);
            dq8(r1.z, o[12], o[13]); dq8(r1.w, o[14], o[15]);
            char* bd = sm + B_BASE + ((kt + 1) & 1) * B_STAGE + b_soff;
#pragma unroll
            for (int j = 0; j < 4; j++)
                reinterpret_cast<uint4*>(bd + j * 16)[0] =
                    make_uint4(o[4 * j], o[4 * j + 1], o[4 * j + 2], o[4 * j + 3]);
        }
        // 2. LDG B(kt+3) into qb[kt&1]  (distance 3)
        if (kt < KT - 3) {
            qb[kt & 1][0] = reinterpret_cast<const uint4*>(bgm + (kt + 3) * BK)[0];
            qb[kt & 1][1] = reinterpret_cast<const uint4*>(bgm + (kt + 3) * BK)[1];
        }
        // 3. cp.async A(kt+2) into stage (kt+2)%3
        if (kt < KT - 2) {
            const uint32_t As = sb + (uint32_t)(((kt + 2) % 3) * A_STAGE);
            const int ke = (kt + 2) * BK;
            cpa16(As + a_soff, agm_hi + ke);
            cpa16(As + a_soff + 16, agm_hi + ke + 8);
            cpa16(As + A_LO + a_soff, agm_lo + ke);
            cpa16(As + A_LO + a_soff + 16, agm_lo + ke + 8);
        }
        cpa_commit();

        // 4. compute (A stage kt%3, B stage kt&1): 4x k16, hi + lo
        {
            const uint32_t Ab = sb + (uint32_t)((kt % 3) * A_STAGE);
            const uint32_t Bb = sb + B_BASE + (uint32_t)((kt & 1) * B_STAGE);
#pragma unroll
            for (int kk = 0; kk < 4; kk++) {
                const uint32_t kb = (uint32_t)(kk * 32);
                uint32_t ah[2][4], al[2][4], b[4][2];
#pragma unroll
                for (int mi = 0; mi < 2; mi++)
                    ldsm_x4(Ab + aoff + mi * (16 * PITCH) + kb, ah[mi]);
#pragma unroll
                for (int nj = 0; nj < 2; nj++) {
                    uint32_t t[4];
                    ldsm_x4(Bb + boff4 + nj * (16 * PITCH) + kb, t);
                    b[2 * nj][0] = t[0]; b[2 * nj][1] = t[1];
                    b[2 * nj + 1][0] = t[2]; b[2 * nj + 1][1] = t[3];
                }
#pragma unroll
                for (int mi = 0; mi < 2; mi++)
#pragma unroll
                    for (int ni = 0; ni < 4; ni++)
                        mma_bf16(pac[mi][ni], ah[mi], b[ni]);
#pragma unroll
                for (int mi = 0; mi < 2; mi++)
                    ldsm_x4(Ab + A_LO + aoff + mi * (16 * PITCH) + kb, al[mi]);
#pragma unroll
                for (int mi = 0; mi < 2; mi++)
#pragma unroll
                    for (int ni = 0; ni < 4; ni++)
                        mma_bf16(pac[mi][ni], al[mi], b[ni]);
            }
        }

        // 5. per-group rescale (group = 128 k = 2 iters)
        if (kt & 1) {
            const int g = kt >> 1;
#pragma unroll
            for (int ni = 0; ni < 4; ni++) {
                float s0 = scp[ni * 8 * G_DIM + g];
                float s1 = scp[ni * 8 * G_DIM + G_DIM + g];
#pragma unroll
                for (int mi = 0; mi < 2; mi++) {
                    tac[mi][ni][0] = fmaf(pac[mi][ni][0], s0, tac[mi][ni][0]);
                    tac[mi][ni][1] = fmaf(pac[mi][ni][1], s1, tac[mi][ni][1]);
                    tac[mi][ni][2] = fmaf(pac[mi][ni][2], s0, tac[mi][ni][2]);
                    tac[mi][ni][3] = fmaf(pac[mi][ni][3], s1, tac[mi][ni][3]);
                    pac[mi][ni][0] = 0.f; pac[mi][ni][1] = 0.f;
                    pac[mi][ni][2] = 0.f; pac[mi][ni][3] = 0.f;
                }
            }
        }

        cpa_wait1();
        __syncthreads();
    }

    // ---- LoRA k16 step (pac zero after final rescale) ----
    {
        uint32_t ah[2][4], b[4][2];
#pragma unroll
        for (int mi = 0; mi < 2; mi++)
            ldsm_x4(sb + SXA + (uint32_t)((wm + mi * 16 + (lane & 15)) * 32
                                          + ((lane >> 4) << 4)), ah[mi]);
#pragma unroll
        for (int ni = 0; ni < 4; ni++)
            ldsm_x2(sb + SLB + (uint32_t)((wn + ni * 8 + (lane & 7)) * 32
                                          + (((lane >> 3) & 1) << 4)), b[ni]);
#pragma unroll
        for (int mi = 0; mi < 2; mi++)
#pragma unroll
            for (int ni = 0; ni < 4; ni++) {
                mma_bf16(pac[mi][ni], ah[mi], b[ni]);
#pragma unroll
                for (int j = 0; j < 4; j++)
                    tac[mi][ni][j] += pac[mi][ni][j];
            }
    }

    // ---- store ----
    {
        const int r  = lane >> 2;
        const int c2 = (lane & 3) * 2;
#pragma unroll
        for (int mi = 0; mi < 2; mi++) {
#pragma unroll
            for (int ni = 0; ni < 4; ni++) {
                const int m = m0 + wm + mi * 16 + r;
                const int n = n0 + wn + ni * 8 + c2;
                float* p = out + (size_t)m * N_DIM + n;
                *reinterpret_cast<float2*>(p) =
                    make_float2(tac[mi][ni][0], tac[mi][ni][1]);
                *reinterpret_cast<float2*>(p + 8 * (size_t)N_DIM) =
                    make_float2(tac[mi][ni][2], tac[mi][ni][3]);
            }
        }
    }
}

// ---------------------------------------------------------------------------
// kernel_launch — inputs: x, qweight, scales, zeros, lora_A, lora_B
// ---------------------------------------------------------------------------
extern "C" void kernel_launch(void* const* d_in, const int* in_sizes, int n_in,
                              void* d_out, int out_size) {
    const float* x      = (const float*)d_in[0];
    const int*   qw     = (const int*)  d_in[1];
    const float* scales = (const float*)d_in[2];
    const int*   zeros  = (const int*)  d_in[3];
    const float* loraA  = (const float*)d_in[4];
    const float* loraB  = (const float*)d_in[5];
    float*       out    = (float*)d_out;

    cudaFuncSetAttribute(gptq_lora_mma,
                         cudaFuncAttributeMaxDynamicSharedMemorySize, SMEM_BYTES);

    xsplit_kernel<<<(M_DIM * K_DIM) / (256 * 4), 256>>>(x);
    pack_qw8<<<(int)(((size_t)N_DIM * K_DIM) / (256 * 8)), 256>>>(qw, zeros);
    lora_xa_kernel<<<M_DIM, 256>>>(x, loraA);

    dim3 grid(M_DIM / BM, N_DIM / BN);   // (4, 86): m fastest -> qweight L2 dedup
    gptq_lora_mma<<<grid, 256, SMEM_BYTES>>>(scales, loraB, out);
}